// round 3
// baseline (speedup 1.0000x reference)
#include <cuda_runtime.h>

#define N_NODES 100000
#define N_EDGES 1600000
#define DIM 64
#define SCAN_CHUNK 1024
#define NCH ((N_NODES + SCAN_CHUNK - 1) / SCAN_CHUNK)   // 98

// scratch (allocation-free: device globals)
__device__ float g_h[(size_t)N_NODES * DIM];   // (1+eps)*x + agg
__device__ float g_t[(size_t)N_NODES * DIM];   // h@W1 + b1
__device__ float g_sum[DIM];
__device__ float g_sq[DIM];
__device__ int   g_deg[N_NODES];
__device__ int   g_off[N_NODES];
__device__ int   g_cur[N_NODES];
__device__ unsigned long long g_state[NCH];    // (inclusive_sum<<32)|1
__device__ unsigned g_es[N_EDGES];             // (attr<<28) | src

#define PACK2(d, lo, hi)  asm("mov.b64 %0, {%1, %2};" : "=l"(d) : "f"(lo), "f"(hi))
#define UNPACK2(lo, hi, s) asm("mov.b64 {%0, %1}, %2;" : "=f"(lo), "=f"(hi) : "l"(s))
#define FMA2(acc, a, b)   asm("fma.rn.f32x2 %0, %1, %2, %0;" : "+l"(acc) : "l"(a), "l"(b))

// ---------------------------------------------------------------------------
// K0: zero degree counters, scan state, BN accumulators
// ---------------------------------------------------------------------------
__global__ void zero_kernel() {
    int i = blockIdx.x * 256 + threadIdx.x;
    if (i < N_NODES) g_deg[i] = 0;
    if (i < NCH) g_state[i] = 0ull;
    if (i < DIM) { g_sum[i] = 0.0f; g_sq[i] = 0.0f; }
}

// ---------------------------------------------------------------------------
// K1: histogram of dst
// ---------------------------------------------------------------------------
__global__ void hist_kernel(const int* __restrict__ ei) {
    int e = blockIdx.x * 256 + threadIdx.x;
    if (e < N_EDGES) atomicAdd(&g_deg[ei[N_EDGES + e]], 1);
}

// ---------------------------------------------------------------------------
// K2: single-kernel exclusive scan (decoupled lookback).
// 98 blocks x 1024 threads; all blocks resident in wave 1 -> no deadlock.
// ---------------------------------------------------------------------------
__global__ void scan_kernel() {
    __shared__ int warp_sums[32];
    __shared__ int s_base;
    int idx = blockIdx.x * SCAN_CHUNK + threadIdx.x;
    int d = (idx < N_NODES) ? g_deg[idx] : 0;

    int v = d;
    int lane = threadIdx.x & 31, wid = threadIdx.x >> 5;
    #pragma unroll
    for (int o = 1; o < 32; o <<= 1) {
        int t = __shfl_up_sync(0xFFFFFFFFu, v, o);
        if (lane >= o) v += t;
    }
    if (lane == 31) warp_sums[wid] = v;
    __syncthreads();
    if (wid == 0) {
        int s = warp_sums[lane];
        #pragma unroll
        for (int o = 1; o < 32; o <<= 1) {
            int t = __shfl_up_sync(0xFFFFFFFFu, s, o);
            if (lane >= o) s += t;
        }
        warp_sums[lane] = s;
    }
    __syncthreads();
    int incl  = v + (wid > 0 ? warp_sums[wid - 1] : 0);
    int total = warp_sums[31];

    if (threadIdx.x == 0) {
        int base = 0;
        if (blockIdx.x > 0) {
            unsigned long long st;
            do {
                st = *(volatile unsigned long long*)&g_state[blockIdx.x - 1];
            } while (!(st & 1ull));
            base = (int)(st >> 32);
        }
        unsigned long long mine =
            (((unsigned long long)(unsigned)(base + total)) << 32) | 1ull;
        atomicExch(&g_state[blockIdx.x], mine);
        s_base = base;
    }
    __syncthreads();
    int ex = s_base + incl - d;
    if (idx < N_NODES) { g_off[idx] = ex; g_cur[idx] = ex; }
}

// ---------------------------------------------------------------------------
// K3: scatter packed (attr,src) into CSR slots
// ---------------------------------------------------------------------------
__global__ void scatter_kernel(const int* __restrict__ ei, const int* __restrict__ ea) {
    int e = blockIdx.x * 256 + threadIdx.x;
    if (e >= N_EDGES) return;
    int src = ei[e];
    int dst = ei[N_EDGES + e];
    unsigned at = (unsigned)ea[e];
    int pos = atomicAdd(&g_cur[dst], 1);
    g_es[pos] = (unsigned)src | (at << 28);
}

// ---------------------------------------------------------------------------
// K4: aggregate — per node, register-accumulate relu(x[src]+emb[attr]),
//     write h = (1+eps)*x + agg once. 16 lanes per node (float4 each), MLP=4.
// ---------------------------------------------------------------------------
__global__ void agg_kernel(const float* __restrict__ x, const float* __restrict__ emb,
                           const float* __restrict__ eps) {
    __shared__ float s_emb[4 * DIM];
    s_emb[threadIdx.x] = emb[threadIdx.x];   // 256 threads == 256 floats
    __syncthreads();

    unsigned gt = blockIdx.x * 256u + threadIdx.x;
    unsigned n = gt >> 4;
    unsigned lane = gt & 15u;
    if (n >= N_NODES) return;

    int off = g_off[n];
    int deg = g_deg[n];
    float s = 1.0f + __ldg(eps);

    float4 acc = *(const float4*)(x + (size_t)n * DIM + lane * 4);
    acc.x *= s; acc.y *= s; acc.z *= s; acc.w *= s;

    int j = 0;
    for (; j + 4 <= deg; j += 4) {
        unsigned p0 = __ldg(g_es + off + j);
        unsigned p1 = __ldg(g_es + off + j + 1);
        unsigned p2 = __ldg(g_es + off + j + 2);
        unsigned p3 = __ldg(g_es + off + j + 3);
        float4 v0 = *(const float4*)(x + (size_t)(p0 & 0x0FFFFFFFu) * DIM + lane * 4);
        float4 v1 = *(const float4*)(x + (size_t)(p1 & 0x0FFFFFFFu) * DIM + lane * 4);
        float4 v2 = *(const float4*)(x + (size_t)(p2 & 0x0FFFFFFFu) * DIM + lane * 4);
        float4 v3 = *(const float4*)(x + (size_t)(p3 & 0x0FFFFFFFu) * DIM + lane * 4);
        float4 e0 = *(const float4*)(s_emb + (p0 >> 28) * DIM + lane * 4);
        float4 e1 = *(const float4*)(s_emb + (p1 >> 28) * DIM + lane * 4);
        float4 e2 = *(const float4*)(s_emb + (p2 >> 28) * DIM + lane * 4);
        float4 e3 = *(const float4*)(s_emb + (p3 >> 28) * DIM + lane * 4);
        acc.x += fmaxf(v0.x + e0.x, 0.0f) + fmaxf(v1.x + e1.x, 0.0f)
               + fmaxf(v2.x + e2.x, 0.0f) + fmaxf(v3.x + e3.x, 0.0f);
        acc.y += fmaxf(v0.y + e0.y, 0.0f) + fmaxf(v1.y + e1.y, 0.0f)
               + fmaxf(v2.y + e2.y, 0.0f) + fmaxf(v3.y + e3.y, 0.0f);
        acc.z += fmaxf(v0.z + e0.z, 0.0f) + fmaxf(v1.z + e1.z, 0.0f)
               + fmaxf(v2.z + e2.z, 0.0f) + fmaxf(v3.z + e3.z, 0.0f);
        acc.w += fmaxf(v0.w + e0.w, 0.0f) + fmaxf(v1.w + e1.w, 0.0f)
               + fmaxf(v2.w + e2.w, 0.0f) + fmaxf(v3.w + e3.w, 0.0f);
    }
    for (; j < deg; j++) {
        unsigned p0 = __ldg(g_es + off + j);
        float4 v0 = *(const float4*)(x + (size_t)(p0 & 0x0FFFFFFFu) * DIM + lane * 4);
        float4 e0 = *(const float4*)(s_emb + (p0 >> 28) * DIM + lane * 4);
        acc.x += fmaxf(v0.x + e0.x, 0.0f);
        acc.y += fmaxf(v0.y + e0.y, 0.0f);
        acc.z += fmaxf(v0.z + e0.z, 0.0f);
        acc.w += fmaxf(v0.w + e0.w, 0.0f);
    }
    *(float4*)(g_h + (size_t)n * DIM + lane * 4) = acc;
}

// ---------------------------------------------------------------------------
// K5/K6: 128x64 tile GEMM, 8x8 per thread, fma.rn.f32x2 inner loop.
// MODE 0: t = g_h @ W1 + b1, write g_t, accumulate column sum/sumsq
// MODE 1: out = relu(t*A + B) @ W2 + b2, BN affine computed from g_sum/g_sq
// ---------------------------------------------------------------------------
#define TILE_R    128
#define IN_STRIDE 132
#define SMEM_FLOATS (DIM * DIM + DIM * IN_STRIDE + 2 * DIM)   // 12672

template <int MODE>
__global__ void gemm_kernel(const float* __restrict__ W, const float* __restrict__ bias,
                            const float* __restrict__ gamma, const float* __restrict__ beta,
                            float* __restrict__ out_ext) {
    extern __shared__ float sm[];
    float* sW   = sm;                              // [64][64]
    float* sIn  = sm + DIM * DIM;                  // [64][IN_STRIDE] k-major
    float* sAff = sm + DIM * DIM + DIM * IN_STRIDE; // [2][64]

    const float* in  = (MODE == 0) ? g_h : g_t;
    float*       out = (MODE == 0) ? g_t : out_ext;

    int t  = threadIdx.x;            // 128 threads
    int r0 = blockIdx.x * TILE_R;

    #pragma unroll
    for (int i = 0; i < 8; i++)
        ((float4*)sW)[t + i * 128] = ((const float4*)W)[t + i * 128];

    if (MODE == 1) {
        if (t < DIM) {
            const float inv = 1.0f / (float)N_NODES;
            float mu  = g_sum[t] * inv;
            float var = g_sq[t] * inv - mu * mu;
            float a   = gamma[t] * rsqrtf(var + 1e-5f);
            sAff[t]       = a;
            sAff[DIM + t] = fmaf(-mu, a, beta[t]);
        }
        __syncthreads();
    }

    // load input tile transposed: thread t owns row r0+t, 16 x LDG.128
    {
        int row = r0 + t;
        bool valid = row < N_NODES;
        const float4* rp = (const float4*)(in + (size_t)row * DIM);
        #pragma unroll
        for (int q = 0; q < 16; q++) {
            float4 v = valid ? __ldg(rp + q) : make_float4(0.f, 0.f, 0.f, 0.f);
            int k0 = q * 4;
            if (MODE == 1) {
                v.x = fmaxf(fmaf(v.x, sAff[k0 + 0], sAff[DIM + k0 + 0]), 0.0f);
                v.y = fmaxf(fmaf(v.y, sAff[k0 + 1], sAff[DIM + k0 + 1]), 0.0f);
                v.z = fmaxf(fmaf(v.z, sAff[k0 + 2], sAff[DIM + k0 + 2]), 0.0f);
                v.w = fmaxf(fmaf(v.w, sAff[k0 + 3], sAff[DIM + k0 + 3]), 0.0f);
            }
            sIn[(k0 + 0) * IN_STRIDE + t] = v.x;
            sIn[(k0 + 1) * IN_STRIDE + t] = v.y;
            sIn[(k0 + 2) * IN_STRIDE + t] = v.z;
            sIn[(k0 + 3) * IN_STRIDE + t] = v.w;
        }
    }
    __syncthreads();

    int rg = t >> 3;  // 0..15
    int cg = t & 7;   // 0..7

    unsigned long long acc2[8][4];
    #pragma unroll
    for (int i = 0; i < 8; i++)
        #pragma unroll
        for (int jp = 0; jp < 4; jp++) acc2[i][jp] = 0ull;

    #pragma unroll 2
    for (int k = 0; k < 64; k++) {
        float4 a0 = *(const float4*)(sIn + k * IN_STRIDE + rg * 8);
        float4 a1 = *(const float4*)(sIn + k * IN_STRIDE + rg * 8 + 4);
        float4 w0 = *(const float4*)(sW  + k * DIM + cg * 8);
        float4 w1 = *(const float4*)(sW  + k * DIM + cg * 8 + 4);
        unsigned long long w2[4];
        PACK2(w2[0], w0.x, w0.y);
        PACK2(w2[1], w0.z, w0.w);
        PACK2(w2[2], w1.x, w1.y);
        PACK2(w2[3], w1.z, w1.w);
        float av[8] = {a0.x, a0.y, a0.z, a0.w, a1.x, a1.y, a1.z, a1.w};
        #pragma unroll
        for (int i = 0; i < 8; i++) {
            unsigned long long ai;
            PACK2(ai, av[i], av[i]);
            #pragma unroll
            for (int jp = 0; jp < 4; jp++)
                FMA2(acc2[i][jp], ai, w2[jp]);
        }
    }

    float bs[8];
    #pragma unroll
    for (int j = 0; j < 8; j++) bs[j] = bias[cg * 8 + j];

    float csum[8], csq[8];
    #pragma unroll
    for (int j = 0; j < 8; j++) { csum[j] = 0.0f; csq[j] = 0.0f; }

    #pragma unroll
    for (int i = 0; i < 8; i++) {
        int row = r0 + rg * 8 + i;
        if (row < N_NODES) {
            float v[8];
            #pragma unroll
            for (int jp = 0; jp < 4; jp++) {
                float lo, hi;
                UNPACK2(lo, hi, acc2[i][jp]);
                v[2 * jp]     = lo + bs[2 * jp];
                v[2 * jp + 1] = hi + bs[2 * jp + 1];
            }
            if (MODE == 0) {
                #pragma unroll
                for (int j = 0; j < 8; j++) { csum[j] += v[j]; csq[j] += v[j] * v[j]; }
            }
            float4 o0 = make_float4(v[0], v[1], v[2], v[3]);
            float4 o1 = make_float4(v[4], v[5], v[6], v[7]);
            *(float4*)(out + (size_t)row * DIM + cg * 8)     = o0;
            *(float4*)(out + (size_t)row * DIM + cg * 8 + 4) = o1;
        }
    }

    if (MODE == 0) {
        __syncthreads();
        float* red = sIn;
        #pragma unroll
        for (int j = 0; j < 8; j++) {
            red[rg * 64 + cg * 8 + j]        = csum[j];
            red[(16 + rg) * 64 + cg * 8 + j] = csq[j];
        }
        __syncthreads();
        if (t < 64) {
            float s = 0.0f;
            #pragma unroll
            for (int g = 0; g < 16; g++) s += red[g * 64 + t];
            atomicAdd(&g_sum[t], s);
        } else {
            int c = t - 64;
            float s = 0.0f;
            #pragma unroll
            for (int g = 0; g < 16; g++) s += red[(16 + g) * 64 + c];
            atomicAdd(&g_sq[c], s);
        }
    }
}

// ---------------------------------------------------------------------------
extern "C" void kernel_launch(void* const* d_in, const int* in_sizes, int n_in,
                              void* d_out, int out_size) {
    const float* x     = (const float*)d_in[0];
    const float* emb   = (const float*)d_in[1];
    const float* eps   = (const float*)d_in[2];
    const float* W1    = (const float*)d_in[3];
    const float* b1    = (const float*)d_in[4];
    const float* gamma = (const float*)d_in[5];
    const float* beta  = (const float*)d_in[6];
    const float* W2    = (const float*)d_in[7];
    const float* b2    = (const float*)d_in[8];
    const int*   ei    = (const int*)d_in[9];
    const int*   ea    = (const int*)d_in[10];
    float*       out   = (float*)d_out;

    const int smem_bytes = SMEM_FLOATS * 4;  // 50688 > 48K: opt in
    cudaFuncSetAttribute(gemm_kernel<0>, cudaFuncAttributeMaxDynamicSharedMemorySize, smem_bytes);
    cudaFuncSetAttribute(gemm_kernel<1>, cudaFuncAttributeMaxDynamicSharedMemorySize, smem_bytes);

    const int eblocks = (N_EDGES + 255) / 256;            // 6250
    zero_kernel<<<(N_NODES + 255) / 256, 256>>>();
    hist_kernel<<<eblocks, 256>>>(ei);
    scan_kernel<<<NCH, SCAN_CHUNK>>>();
    scatter_kernel<<<eblocks, 256>>>(ei, ea);
    agg_kernel<<<(N_NODES * 16 + 255) / 256, 256>>>(x, emb, eps);
    const int gblocks = (N_NODES + TILE_R - 1) / TILE_R;  // 782
    gemm_kernel<0><<<gblocks, 128, smem_bytes>>>(W1, b1, nullptr, nullptr, nullptr);
    gemm_kernel<1><<<gblocks, 128, smem_bytes>>>(W2, b2, gamma, beta, out);
}

// round 4
// speedup vs baseline: 1.2163x; 1.2163x over previous
#include <cuda_runtime.h>

#define N_NODES 100000
#define N_EDGES 1600000
#define DIM 64
#define SCAN_CHUNK 1024
#define NCH ((N_NODES + SCAN_CHUNK - 1) / SCAN_CHUNK)   // 98

// scratch (allocation-free: device globals)
__device__ float g_h[(size_t)N_NODES * DIM];   // (1+eps)*x + agg
__device__ float g_t[(size_t)N_NODES * DIM];   // h@W1 + b1
__device__ float g_sum[DIM];
__device__ float g_sq[DIM];
__device__ int   g_deg[N_NODES];
__device__ int   g_off[N_NODES];
__device__ int   g_cur[N_NODES];
__device__ int   g_csum[NCH];
__device__ unsigned g_es[N_EDGES];             // (attr<<28) | src

#define PACK2(d, lo, hi)  asm("mov.b64 %0, {%1, %2};" : "=l"(d) : "f"(lo), "f"(hi))
#define UNPACK2(lo, hi, s) asm("mov.b64 {%0, %1}, %2;" : "=f"(lo), "=f"(hi) : "l"(s))
#define FMA2(acc, a, b)   asm("fma.rn.f32x2 %0, %1, %2, %0;" : "+l"(acc) : "l"(a), "l"(b))

// ---------------------------------------------------------------------------
// K0: zero degree counters + BN accumulators
// ---------------------------------------------------------------------------
__global__ void zero_kernel() {
    int i = blockIdx.x * 256 + threadIdx.x;
    if (i < N_NODES) g_deg[i] = 0;
    if (i < DIM) { g_sum[i] = 0.0f; g_sq[i] = 0.0f; }
}

// ---------------------------------------------------------------------------
// K1: histogram of dst — 4 edges/thread via int4, REDG (no return)
// ---------------------------------------------------------------------------
__global__ void hist_kernel(const int* __restrict__ ei) {
    int i = blockIdx.x * 256 + threadIdx.x;       // int4 index
    if (i >= N_EDGES / 4) return;
    int4 d = ((const int4*)(ei + N_EDGES))[i];
    atomicAdd(&g_deg[d.x], 1);
    atomicAdd(&g_deg[d.y], 1);
    atomicAdd(&g_deg[d.z], 1);
    atomicAdd(&g_deg[d.w], 1);
}

// ---------------------------------------------------------------------------
// K2a: per-chunk totals (98 blocks x 256, 4 elems/thread)
// ---------------------------------------------------------------------------
__global__ void scanA_kernel() {
    __shared__ int sm[256];
    int base = blockIdx.x * SCAN_CHUNK;
    int s = 0;
    #pragma unroll
    for (int q = 0; q < 4; q++) {
        int idx = base + threadIdx.x + q * 256;
        if (idx < N_NODES) s += g_deg[idx];
    }
    sm[threadIdx.x] = s; __syncthreads();
    for (int st = 128; st > 0; st >>= 1) {
        if (threadIdx.x < st) sm[threadIdx.x] += sm[threadIdx.x + st];
        __syncthreads();
    }
    if (threadIdx.x == 0) g_csum[blockIdx.x] = sm[0];
}

// ---------------------------------------------------------------------------
// K2b: full scan — each block independently reduces its base from g_csum
// (fully parallel, no cross-block dependence), then in-block scan.
// ---------------------------------------------------------------------------
__global__ void scanC_kernel() {
    __shared__ int warp_sums[32];
    __shared__ int sbase[128];
    int idx = blockIdx.x * SCAN_CHUNK + threadIdx.x;
    int d = (idx < N_NODES) ? g_deg[idx] : 0;

    // base = sum of csum[0..blockIdx.x)
    if (threadIdx.x < 128) {
        int v = 0;
        if ((int)threadIdx.x < NCH && (int)threadIdx.x < (int)blockIdx.x)
            v = g_csum[threadIdx.x];
        sbase[threadIdx.x] = v;
    }
    __syncthreads();
    if (threadIdx.x < 64) sbase[threadIdx.x] += sbase[threadIdx.x + 64];
    __syncthreads();
    if (threadIdx.x < 32) {
        int v = sbase[threadIdx.x] + sbase[threadIdx.x + 32];
        #pragma unroll
        for (int o = 16; o > 0; o >>= 1) v += __shfl_down_sync(0xFFFFFFFFu, v, o);
        if (threadIdx.x == 0) sbase[0] = v;
    }

    // in-block inclusive scan of d
    int v = d;
    int lane = threadIdx.x & 31, wid = threadIdx.x >> 5;
    #pragma unroll
    for (int o = 1; o < 32; o <<= 1) {
        int t = __shfl_up_sync(0xFFFFFFFFu, v, o);
        if (lane >= o) v += t;
    }
    if (lane == 31) warp_sums[wid] = v;
    __syncthreads();
    if (wid == 0) {
        int s = warp_sums[lane];
        #pragma unroll
        for (int o = 1; o < 32; o <<= 1) {
            int t = __shfl_up_sync(0xFFFFFFFFu, s, o);
            if (lane >= o) s += t;
        }
        warp_sums[lane] = s;
    }
    __syncthreads();
    int incl = v + (wid > 0 ? warp_sums[wid - 1] : 0);
    int ex = sbase[0] + incl - d;
    if (idx < N_NODES) { g_off[idx] = ex; g_cur[idx] = ex; }
}

// ---------------------------------------------------------------------------
// K3: scatter packed (attr,src) — 4 edges/thread via int4, 4 atomics in flight
// ---------------------------------------------------------------------------
__global__ void scatter_kernel(const int* __restrict__ ei, const int* __restrict__ ea) {
    int i = blockIdx.x * 256 + threadIdx.x;       // int4 index
    if (i >= N_EDGES / 4) return;
    int4 s = ((const int4*)ei)[i];
    int4 d = ((const int4*)(ei + N_EDGES))[i];
    int4 a = ((const int4*)ea)[i];
    int p0 = atomicAdd(&g_cur[d.x], 1);
    int p1 = atomicAdd(&g_cur[d.y], 1);
    int p2 = atomicAdd(&g_cur[d.z], 1);
    int p3 = atomicAdd(&g_cur[d.w], 1);
    g_es[p0] = (unsigned)s.x | ((unsigned)a.x << 28);
    g_es[p1] = (unsigned)s.y | ((unsigned)a.y << 28);
    g_es[p2] = (unsigned)s.z | ((unsigned)a.z << 28);
    g_es[p3] = (unsigned)s.w | ((unsigned)a.w << 28);
}

// ---------------------------------------------------------------------------
// K4: aggregate — per node, register-accumulate relu(x[src]+emb[attr]),
//     write h = (1+eps)*x + agg once. 16 lanes per node (float4 each), MLP=4.
// ---------------------------------------------------------------------------
__global__ void agg_kernel(const float* __restrict__ x, const float* __restrict__ emb,
                           const float* __restrict__ eps) {
    __shared__ float s_emb[4 * DIM];
    s_emb[threadIdx.x] = emb[threadIdx.x];   // 256 threads == 256 floats
    __syncthreads();

    unsigned gt = blockIdx.x * 256u + threadIdx.x;
    unsigned n = gt >> 4;
    unsigned lane = gt & 15u;
    if (n >= N_NODES) return;

    int off = g_off[n];
    int deg = g_deg[n];
    float s = 1.0f + __ldg(eps);

    float4 acc = *(const float4*)(x + (size_t)n * DIM + lane * 4);
    acc.x *= s; acc.y *= s; acc.z *= s; acc.w *= s;

    int j = 0;
    for (; j + 4 <= deg; j += 4) {
        unsigned p0 = __ldg(g_es + off + j);
        unsigned p1 = __ldg(g_es + off + j + 1);
        unsigned p2 = __ldg(g_es + off + j + 2);
        unsigned p3 = __ldg(g_es + off + j + 3);
        float4 v0 = *(const float4*)(x + (size_t)(p0 & 0x0FFFFFFFu) * DIM + lane * 4);
        float4 v1 = *(const float4*)(x + (size_t)(p1 & 0x0FFFFFFFu) * DIM + lane * 4);
        float4 v2 = *(const float4*)(x + (size_t)(p2 & 0x0FFFFFFFu) * DIM + lane * 4);
        float4 v3 = *(const float4*)(x + (size_t)(p3 & 0x0FFFFFFFu) * DIM + lane * 4);
        float4 e0 = *(const float4*)(s_emb + (p0 >> 28) * DIM + lane * 4);
        float4 e1 = *(const float4*)(s_emb + (p1 >> 28) * DIM + lane * 4);
        float4 e2 = *(const float4*)(s_emb + (p2 >> 28) * DIM + lane * 4);
        float4 e3 = *(const float4*)(s_emb + (p3 >> 28) * DIM + lane * 4);
        acc.x += fmaxf(v0.x + e0.x, 0.0f) + fmaxf(v1.x + e1.x, 0.0f)
               + fmaxf(v2.x + e2.x, 0.0f) + fmaxf(v3.x + e3.x, 0.0f);
        acc.y += fmaxf(v0.y + e0.y, 0.0f) + fmaxf(v1.y + e1.y, 0.0f)
               + fmaxf(v2.y + e2.y, 0.0f) + fmaxf(v3.y + e3.y, 0.0f);
        acc.z += fmaxf(v0.z + e0.z, 0.0f) + fmaxf(v1.z + e1.z, 0.0f)
               + fmaxf(v2.z + e2.z, 0.0f) + fmaxf(v3.z + e3.z, 0.0f);
        acc.w += fmaxf(v0.w + e0.w, 0.0f) + fmaxf(v1.w + e1.w, 0.0f)
               + fmaxf(v2.w + e2.w, 0.0f) + fmaxf(v3.w + e3.w, 0.0f);
    }
    for (; j < deg; j++) {
        unsigned p0 = __ldg(g_es + off + j);
        float4 v0 = *(const float4*)(x + (size_t)(p0 & 0x0FFFFFFFu) * DIM + lane * 4);
        float4 e0 = *(const float4*)(s_emb + (p0 >> 28) * DIM + lane * 4);
        acc.x += fmaxf(v0.x + e0.x, 0.0f);
        acc.y += fmaxf(v0.y + e0.y, 0.0f);
        acc.z += fmaxf(v0.z + e0.z, 0.0f);
        acc.w += fmaxf(v0.w + e0.w, 0.0f);
    }
    *(float4*)(g_h + (size_t)n * DIM + lane * 4) = acc;
}

// ---------------------------------------------------------------------------
// K5/K6: 128x64 tile GEMM, 8x8 per thread, fma.rn.f32x2 inner loop.
// MODE 0: t = g_h @ W1 + b1, write g_t, accumulate column sum/sumsq
// MODE 1: out = relu(t*A + B) @ W2 + b2, BN affine computed from g_sum/g_sq
// ---------------------------------------------------------------------------
#define TILE_R    128
#define IN_STRIDE 132
#define SMEM_FLOATS (DIM * DIM + DIM * IN_STRIDE + 2 * DIM)   // 12672

template <int MODE>
__global__ void gemm_kernel(const float* __restrict__ W, const float* __restrict__ bias,
                            const float* __restrict__ gamma, const float* __restrict__ beta,
                            float* __restrict__ out_ext) {
    extern __shared__ float sm[];
    float* sW   = sm;                               // [64][64]
    float* sIn  = sm + DIM * DIM;                   // [64][IN_STRIDE] k-major
    float* sAff = sm + DIM * DIM + DIM * IN_STRIDE; // [2][64]

    const float* in  = (MODE == 0) ? g_h : g_t;
    float*       out = (MODE == 0) ? g_t : out_ext;

    int t  = threadIdx.x;            // 128 threads
    int r0 = blockIdx.x * TILE_R;

    #pragma unroll
    for (int i = 0; i < 8; i++)
        ((float4*)sW)[t + i * 128] = ((const float4*)W)[t + i * 128];

    if (MODE == 1) {
        if (t < DIM) {
            const float inv = 1.0f / (float)N_NODES;
            float mu  = g_sum[t] * inv;
            float var = g_sq[t] * inv - mu * mu;
            float a   = gamma[t] * rsqrtf(var + 1e-5f);
            sAff[t]       = a;
            sAff[DIM + t] = fmaf(-mu, a, beta[t]);
        }
        __syncthreads();
    }

    // load input tile transposed: thread t owns row r0+t, 16 x LDG.128
    {
        int row = r0 + t;
        bool valid = row < N_NODES;
        const float4* rp = (const float4*)(in + (size_t)row * DIM);
        #pragma unroll
        for (int q = 0; q < 16; q++) {
            float4 v = valid ? __ldg(rp + q) : make_float4(0.f, 0.f, 0.f, 0.f);
            int k0 = q * 4;
            if (MODE == 1) {
                v.x = fmaxf(fmaf(v.x, sAff[k0 + 0], sAff[DIM + k0 + 0]), 0.0f);
                v.y = fmaxf(fmaf(v.y, sAff[k0 + 1], sAff[DIM + k0 + 1]), 0.0f);
                v.z = fmaxf(fmaf(v.z, sAff[k0 + 2], sAff[DIM + k0 + 2]), 0.0f);
                v.w = fmaxf(fmaf(v.w, sAff[k0 + 3], sAff[DIM + k0 + 3]), 0.0f);
            }
            sIn[(k0 + 0) * IN_STRIDE + t] = v.x;
            sIn[(k0 + 1) * IN_STRIDE + t] = v.y;
            sIn[(k0 + 2) * IN_STRIDE + t] = v.z;
            sIn[(k0 + 3) * IN_STRIDE + t] = v.w;
        }
    }
    __syncthreads();

    int rg = t >> 3;  // 0..15
    int cg = t & 7;   // 0..7

    unsigned long long acc2[8][4];
    #pragma unroll
    for (int i = 0; i < 8; i++)
        #pragma unroll
        for (int jp = 0; jp < 4; jp++) acc2[i][jp] = 0ull;

    #pragma unroll 2
    for (int k = 0; k < 64; k++) {
        float4 a0 = *(const float4*)(sIn + k * IN_STRIDE + rg * 8);
        float4 a1 = *(const float4*)(sIn + k * IN_STRIDE + rg * 8 + 4);
        float4 w0 = *(const float4*)(sW  + k * DIM + cg * 8);
        float4 w1 = *(const float4*)(sW  + k * DIM + cg * 8 + 4);
        unsigned long long w2[4];
        PACK2(w2[0], w0.x, w0.y);
        PACK2(w2[1], w0.z, w0.w);
        PACK2(w2[2], w1.x, w1.y);
        PACK2(w2[3], w1.z, w1.w);
        float av[8] = {a0.x, a0.y, a0.z, a0.w, a1.x, a1.y, a1.z, a1.w};
        #pragma unroll
        for (int i = 0; i < 8; i++) {
            unsigned long long ai;
            PACK2(ai, av[i], av[i]);
            #pragma unroll
            for (int jp = 0; jp < 4; jp++)
                FMA2(acc2[i][jp], ai, w2[jp]);
        }
    }

    float bs[8];
    #pragma unroll
    for (int j = 0; j < 8; j++) bs[j] = bias[cg * 8 + j];

    float csum[8], csq[8];
    #pragma unroll
    for (int j = 0; j < 8; j++) { csum[j] = 0.0f; csq[j] = 0.0f; }

    #pragma unroll
    for (int i = 0; i < 8; i++) {
        int row = r0 + rg * 8 + i;
        if (row < N_NODES) {
            float v[8];
            #pragma unroll
            for (int jp = 0; jp < 4; jp++) {
                float lo, hi;
                UNPACK2(lo, hi, acc2[i][jp]);
                v[2 * jp]     = lo + bs[2 * jp];
                v[2 * jp + 1] = hi + bs[2 * jp + 1];
            }
            if (MODE == 0) {
                #pragma unroll
                for (int j = 0; j < 8; j++) { csum[j] += v[j]; csq[j] += v[j] * v[j]; }
            }
            float4 o0 = make_float4(v[0], v[1], v[2], v[3]);
            float4 o1 = make_float4(v[4], v[5], v[6], v[7]);
            *(float4*)(out + (size_t)row * DIM + cg * 8)     = o0;
            *(float4*)(out + (size_t)row * DIM + cg * 8 + 4) = o1;
        }
    }

    if (MODE == 0) {
        __syncthreads();
        float* red = sIn;
        #pragma unroll
        for (int j = 0; j < 8; j++) {
            red[rg * 64 + cg * 8 + j]        = csum[j];
            red[(16 + rg) * 64 + cg * 8 + j] = csq[j];
        }
        __syncthreads();
        if (t < 64) {
            float s = 0.0f;
            #pragma unroll
            for (int g = 0; g < 16; g++) s += red[g * 64 + t];
            atomicAdd(&g_sum[t], s);
        } else {
            int c = t - 64;
            float s = 0.0f;
            #pragma unroll
            for (int g = 0; g < 16; g++) s += red[(16 + g) * 64 + c];
            atomicAdd(&g_sq[c], s);
        }
    }
}

// ---------------------------------------------------------------------------
extern "C" void kernel_launch(void* const* d_in, const int* in_sizes, int n_in,
                              void* d_out, int out_size) {
    const float* x     = (const float*)d_in[0];
    const float* emb   = (const float*)d_in[1];
    const float* eps   = (const float*)d_in[2];
    const float* W1    = (const float*)d_in[3];
    const float* b1    = (const float*)d_in[4];
    const float* gamma = (const float*)d_in[5];
    const float* beta  = (const float*)d_in[6];
    const float* W2    = (const float*)d_in[7];
    const float* b2    = (const float*)d_in[8];
    const int*   ei    = (const int*)d_in[9];
    const int*   ea    = (const int*)d_in[10];
    float*       out   = (float*)d_out;

    const int smem_bytes = SMEM_FLOATS * 4;  // 50688 > 48K: opt in
    cudaFuncSetAttribute(gemm_kernel<0>, cudaFuncAttributeMaxDynamicSharedMemorySize, smem_bytes);
    cudaFuncSetAttribute(gemm_kernel<1>, cudaFuncAttributeMaxDynamicSharedMemorySize, smem_bytes);

    const int e4blocks = (N_EDGES / 4 + 255) / 256;       // 1563
    zero_kernel<<<(N_NODES + 255) / 256, 256>>>();
    hist_kernel<<<e4blocks, 256>>>(ei);
    scanA_kernel<<<NCH, 256>>>();
    scanC_kernel<<<NCH, SCAN_CHUNK>>>();
    scatter_kernel<<<e4blocks, 256>>>(ei, ea);
    agg_kernel<<<(N_NODES * 16 + 255) / 256, 256>>>(x, emb, eps);
    const int gblocks = (N_NODES + TILE_R - 1) / TILE_R;  // 782
    gemm_kernel<0><<<gblocks, 128, smem_bytes>>>(W1, b1, nullptr, nullptr, nullptr);
    gemm_kernel<1><<<gblocks, 128, smem_bytes>>>(W2, b2, gamma, beta, out);
}